// round 3
// baseline (speedup 1.0000x reference)
#include <cuda_runtime.h>
#include <math.h>

// Problem constants (fixed shapes: B=16, C=1, T=8192, F=65, WINDOW=64)
#define T_DIM     8192
#define B_DIM     16
#define FQ        65          // rfft bins
#define NT        33          // unique t values 0..32 after even/odd + mirror
#define ROWS      69          // input rows per tile (TILE_H + 5 overlap)
#define TILE_H    64          // output rows per block
#define TRUE_LEN  (T_DIM - 5) // 8187 output rows per batch
#define XS_STRIDE 66          // padded stride for Xs (float2-aligned rows)
#define YS_STRIDE 66          // padded stride for Y (t in 0..64)

// Packed cosine table: g_C[t*64 + 2i] = CE[t][i], g_C[t*64 + 2i + 1] = CO[t][i]
//   CE[t][i] = a_i * cos(pi*(2*i*t)/64), i=0..31, a = 1 for i==0 else 2
//   CO[t][i] = 2 * cos(pi*((2i+1)*t)/64), i=0..31
// Nyquist (freq 64) column kept separate: g_CE32[t] = cos(pi*t)
// irfft row (norm='forward', real input spectrum -> even signal):
//   Y[t] = E[t]+O[t],  Y[64-t] = E[t]-O[t]  (t = 0..32),  Y[t] = Y[128-t].
__device__ float g_C[NT * 64];
__device__ float g_CE32[NT];

__global__ void init_tables_kernel() {
    int idx = blockIdx.x * blockDim.x + threadIdx.x;
    if (idx < NT * 64) {
        int t = idx / 64, q = idx % 64, i = q >> 1;
        if ((q & 1) == 0) {
            double a = (i == 0) ? 1.0 : 2.0;
            int m = (2 * i * t) & 127;   // phase in units of pi/64, period 128
            g_C[idx] = (float)(a * cos(M_PI * (double)m / 64.0));
        } else {
            int m = ((2 * i + 1) * t) & 127;
            g_C[idx] = (float)(2.0 * cos(M_PI * (double)m / 64.0));
        }
    }
    int idx2 = idx - NT * 64;
    if (idx2 >= 0 && idx2 < NT) {
        g_CE32[idx2] = (idx2 & 1) ? -1.0f : 1.0f;   // cos(pi * t)
    }
}

__global__ __launch_bounds__(256, 4) void subband_kernel(
    const float* __restrict__ inp,   // [B, 1, T, FQ]
    const float* __restrict__ filt,  // [384]
    float* __restrict__ out)         // [B, 1, TRUE_LEN*64]
{
    __shared__ __align__(16) float Xs[ROWS * XS_STRIDE]; // staged input rows (padded)
    __shared__ __align__(16) float Ys[ROWS * YS_STRIDE]; // per-row irfft, t = 0..64
    __shared__ __align__(16) float sC[NT * 64];          // interleaved CE/CO
    __shared__ float sC32[NT];
    __shared__ float sF[6 * 64];

    const int tid  = threadIdx.x;
    const int b    = blockIdx.y;
    const int base = blockIdx.x * TILE_H;

    // ---- Phase 1: stage tables + input tile into smem (coalesced gmem reads) ----
    for (int i = tid; i < NT * 64; i += 256) sC[i] = g_C[i];
    if (tid < NT) sC32[tid] = g_CE32[tid];
    if (tid < 128) {
        sF[tid]       = filt[tid];
        sF[tid + 128] = filt[tid + 128];
        sF[tid + 256] = filt[tid + 256];
    }
    int nrows = T_DIM - base; if (nrows > ROWS) nrows = ROWS;
    const float* src = inp + ((size_t)b * T_DIM + base) * FQ;
    for (int i = tid; i < nrows * FQ; i += 256) {
        int r = i / FQ, c = i - r * FQ;
        Xs[r * XS_STRIDE + c] = src[i];
    }
    __syncthreads();

    // ---- Phase 2: per-row irfft via even/odd cosine transform ----
    // 11 t-threads (t = tt, tt+11, tt+22) x 23 row-groups (r = rg, rg+23, rg+46)
    if (tid < 253) {
        const int tt = tid % 11;
        const int rg = tid / 11;

        float aE00=0.f,aE01=0.f,aE02=0.f, aE10=0.f,aE11=0.f,aE12=0.f, aE20=0.f,aE21=0.f,aE22=0.f;
        float aO00=0.f,aO01=0.f,aO02=0.f, aO10=0.f,aO11=0.f,aO12=0.f, aO20=0.f,aO21=0.f,aO22=0.f;

        const float2* c0 = (const float2*)&sC[tt * 64];
        const float2* c1 = (const float2*)&sC[(tt + 11) * 64];
        const float2* c2 = (const float2*)&sC[(tt + 22) * 64];
        const float2* x0 = (const float2*)&Xs[rg * XS_STRIDE];
        const float2* x1 = (const float2*)&Xs[(rg + 23) * XS_STRIDE];
        const float2* x2 = (const float2*)&Xs[(rg + 46) * XS_STRIDE];

        #pragma unroll 8
        for (int i = 0; i < 32; i++) {
            float2 cc0 = c0[i], cc1 = c1[i], cc2 = c2[i];
            float2 v0 = x0[i], v1 = x1[i], v2 = x2[i];
            aE00 += cc0.x * v0.x; aO00 += cc0.y * v0.y;
            aE01 += cc0.x * v1.x; aO01 += cc0.y * v1.y;
            aE02 += cc0.x * v2.x; aO02 += cc0.y * v2.y;
            aE10 += cc1.x * v0.x; aO10 += cc1.y * v0.y;
            aE11 += cc1.x * v1.x; aO11 += cc1.y * v1.y;
            aE12 += cc1.x * v2.x; aO12 += cc1.y * v2.y;
            aE20 += cc2.x * v0.x; aO20 += cc2.y * v0.y;
            aE21 += cc2.x * v1.x; aO21 += cc2.y * v1.y;
            aE22 += cc2.x * v2.x; aO22 += cc2.y * v2.y;
        }
        { // tail: Nyquist bin (freq 64)
            float e0 = sC32[tt], e1 = sC32[tt + 11], e2 = sC32[tt + 22];
            float xe0 = Xs[rg * XS_STRIDE + 64];
            float xe1 = Xs[(rg + 23) * XS_STRIDE + 64];
            float xe2 = Xs[(rg + 46) * XS_STRIDE + 64];
            aE00 += e0 * xe0; aE01 += e0 * xe1; aE02 += e0 * xe2;
            aE10 += e1 * xe0; aE11 += e1 * xe1; aE12 += e1 * xe2;
            aE20 += e2 * xe0; aE21 += e2 * xe1; aE22 += e2 * xe2;
        }

        // scatter Y[t] = E+O, Y[64-t] = E-O
        const int t0 = tt, t1 = tt + 11, t2 = tt + 22;
        const int r0 = rg, r1 = rg + 23, r2 = rg + 46;
        Ys[r0*YS_STRIDE + t0]      = aE00 + aO00;
        Ys[r0*YS_STRIDE + 64 - t0] = aE00 - aO00;
        Ys[r1*YS_STRIDE + t0]      = aE01 + aO01;
        Ys[r1*YS_STRIDE + 64 - t0] = aE01 - aO01;
        Ys[r2*YS_STRIDE + t0]      = aE02 + aO02;
        Ys[r2*YS_STRIDE + 64 - t0] = aE02 - aO02;
        Ys[r0*YS_STRIDE + t1]      = aE10 + aO10;
        Ys[r0*YS_STRIDE + 64 - t1] = aE10 - aO10;
        Ys[r1*YS_STRIDE + t1]      = aE11 + aO11;
        Ys[r1*YS_STRIDE + 64 - t1] = aE11 - aO11;
        Ys[r2*YS_STRIDE + t1]      = aE12 + aO12;
        Ys[r2*YS_STRIDE + 64 - t1] = aE12 - aO12;
        Ys[r0*YS_STRIDE + t2]      = aE20 + aO20;
        Ys[r0*YS_STRIDE + 64 - t2] = aE20 - aO20;
        Ys[r1*YS_STRIDE + t2]      = aE21 + aO21;
        Ys[r1*YS_STRIDE + 64 - t2] = aE21 - aO21;
        Ys[r2*YS_STRIDE + t2]      = aE22 + aO22;
        Ys[r2*YS_STRIDE + 64 - t2] = aE22 - aO22;
    }
    __syncthreads();

    // ---- Phase 3: polyphase overlap-add ----
    // out[b,h,j] = (1/512) * sum_k F[64k+j] * Y_{h+5-k}[(64k+j) & 127]
    //   k even -> Y[j], k odd -> Y[64-j] (mirror symmetry)
    const int j  = tid & 63;
    const int hg = tid >> 6;   // 4 h-groups of 16 rows
    const float f0 = sF[j],       f1 = sF[64 + j],  f2 = sF[128 + j];
    const float f3 = sF[192 + j], f4 = sF[256 + j], f5 = sF[320 + j];
    float* outb = out + (size_t)b * ((size_t)TRUE_LEN * 64);

    #pragma unroll 4
    for (int hh = 0; hh < 16; hh++) {
        int hl = hg * 16 + hh;
        int h  = base + hl;
        if (h < TRUE_LEN) {
            float acc = f0 * Ys[(hl + 5) * YS_STRIDE + j]
                      + f1 * Ys[(hl + 4) * YS_STRIDE + 64 - j]
                      + f2 * Ys[(hl + 3) * YS_STRIDE + j]
                      + f3 * Ys[(hl + 2) * YS_STRIDE + 64 - j]
                      + f4 * Ys[(hl + 1) * YS_STRIDE + j]
                      + f5 * Ys[(hl + 0) * YS_STRIDE + 64 - j];
            outb[(size_t)h * 64 + j] = acc * (1.0f / 512.0f);
        }
    }
}

extern "C" void kernel_launch(void* const* d_in, const int* in_sizes, int n_in,
                              void* d_out, int out_size) {
    const float* inp  = (const float*)d_in[0];
    const float* filt = (const float*)d_in[1];
    float* out = (float*)d_out;

    init_tables_kernel<<<9, 256>>>();                   // 2145 table entries
    dim3 grid((TRUE_LEN + TILE_H - 1) / TILE_H, B_DIM); // 128 x 16
    subband_kernel<<<grid, 256>>>(inp, filt, out);
}

// round 4
// speedup vs baseline: 2.4907x; 2.4907x over previous
#include <cuda_runtime.h>
#include <math.h>

// Problem constants (fixed shapes: B=16, C=1, T=8192, F=65, WINDOW=64)
#define T_DIM     8192
#define B_DIM     16
#define FQ        65          // rfft bins
#define NT        33          // unique t values 0..32 after even/odd + mirror
#define ROWS      69          // input rows per tile (TILE_H + 5 overlap)
#define TILE_H    64          // output rows per block
#define TRUE_LEN  (T_DIM - 5) // 8187 output rows per batch
#define XS_STRIDE 66          // padded stride for Xs (float2-aligned, bank-skewed)
#define YS_STRIDE 66          // padded stride for Y (t in 0..64)
#define C_STRIDE  66          // padded stride for coefficient table (bank-skewed!)

// Packed cosine table row t: sC[t*C_STRIDE + 2i] = CE[t][i], [.. + 2i+1] = CO[t][i]
//   CE[t][i] = a_i * cos(pi*(2*i*t)/64), i=0..31, a = 1 for i==0 else 2
//   CO[t][i] = 2 * cos(pi*((2i+1)*t)/64), i=0..31
// Nyquist (freq 64) column separate: g_CE32[t] = cos(pi*t)
// irfft row (norm='forward', real input spectrum -> even signal):
//   Y[t] = E[t]+O[t],  Y[64-t] = E[t]-O[t]  (t = 0..32),  Y[t] = Y[128-t].
__device__ float g_C[NT * C_STRIDE];
__device__ float g_CE32[NT];

__global__ void init_tables_kernel() {
    int idx = blockIdx.x * blockDim.x + threadIdx.x;
    if (idx < NT * C_STRIDE) {
        int t = idx / C_STRIDE, q = idx % C_STRIDE, i = q >> 1;
        if (q >= 64) { g_C[idx] = 0.0f; }
        else if ((q & 1) == 0) {
            double a = (i == 0) ? 1.0 : 2.0;
            int m = (2 * i * t) & 127;   // phase in units of pi/64, period 128
            g_C[idx] = (float)(a * cos(M_PI * (double)m / 64.0));
        } else {
            int m = ((2 * i + 1) * t) & 127;
            g_C[idx] = (float)(2.0 * cos(M_PI * (double)m / 64.0));
        }
    }
    int idx2 = idx - NT * C_STRIDE;
    if (idx2 >= 0 && idx2 < NT) {
        g_CE32[idx2] = (idx2 & 1) ? -1.0f : 1.0f;   // cos(pi * t)
    }
}

__global__ __launch_bounds__(256, 4) void subband_kernel(
    const float* __restrict__ inp,   // [B, 1, T, FQ]
    const float* __restrict__ filt,  // [384]
    float* __restrict__ out)         // [B, 1, TRUE_LEN*64]
{
    __shared__ __align__(16) float Xs[ROWS * XS_STRIDE]; // staged input rows (padded)
    __shared__ __align__(16) float Ys[ROWS * YS_STRIDE]; // per-row irfft, t = 0..64
    __shared__ __align__(16) float sC[NT * C_STRIDE];    // interleaved CE/CO, skewed
    __shared__ float sC32[NT];
    __shared__ float sF[6 * 64];

    const int tid  = threadIdx.x;
    const int b    = blockIdx.y;
    const int base = blockIdx.x * TILE_H;

    // ---- Phase 1: stage tables + input tile into smem (coalesced gmem reads) ----
    for (int i = tid; i < NT * C_STRIDE; i += 256) sC[i] = g_C[i];
    if (tid < NT) sC32[tid] = g_CE32[tid];
    if (tid < 128) {
        sF[tid]       = filt[tid];
        sF[tid + 128] = filt[tid + 128];
        sF[tid + 256] = filt[tid + 256];
    }
    int nrows = T_DIM - base; if (nrows > ROWS) nrows = ROWS;
    const float* src = inp + ((size_t)b * T_DIM + base) * FQ;
    for (int i = tid; i < nrows * FQ; i += 256) {
        int r = i / FQ, c = i - r * FQ;
        Xs[r * XS_STRIDE + c] = src[i];
    }
    __syncthreads();

    // ---- Phase 2: per-row irfft via even/odd cosine transform ----
    // 11 t-threads (t = tt, tt+11, tt+22) x 23 row-groups (r = rg, rg+23, rg+46)
    if (tid < 253) {
        const int tt = tid % 11;
        const int rg = tid / 11;

        float aE00=0.f,aE01=0.f,aE02=0.f, aE10=0.f,aE11=0.f,aE12=0.f, aE20=0.f,aE21=0.f,aE22=0.f;
        float aO00=0.f,aO01=0.f,aO02=0.f, aO10=0.f,aO11=0.f,aO12=0.f, aO20=0.f,aO21=0.f,aO22=0.f;

        const float2* c0 = (const float2*)&sC[tt * C_STRIDE];
        const float2* c1 = (const float2*)&sC[(tt + 11) * C_STRIDE];
        const float2* c2 = (const float2*)&sC[(tt + 22) * C_STRIDE];
        const float2* x0 = (const float2*)&Xs[rg * XS_STRIDE];
        const float2* x1 = (const float2*)&Xs[(rg + 23) * XS_STRIDE];
        const float2* x2 = (const float2*)&Xs[(rg + 46) * XS_STRIDE];

        #pragma unroll 8
        for (int i = 0; i < 32; i++) {
            float2 cc0 = c0[i], cc1 = c1[i], cc2 = c2[i];
            float2 v0 = x0[i], v1 = x1[i], v2 = x2[i];
            aE00 += cc0.x * v0.x; aO00 += cc0.y * v0.y;
            aE01 += cc0.x * v1.x; aO01 += cc0.y * v1.y;
            aE02 += cc0.x * v2.x; aO02 += cc0.y * v2.y;
            aE10 += cc1.x * v0.x; aO10 += cc1.y * v0.y;
            aE11 += cc1.x * v1.x; aO11 += cc1.y * v1.y;
            aE12 += cc1.x * v2.x; aO12 += cc1.y * v2.y;
            aE20 += cc2.x * v0.x; aO20 += cc2.y * v0.y;
            aE21 += cc2.x * v1.x; aO21 += cc2.y * v1.y;
            aE22 += cc2.x * v2.x; aO22 += cc2.y * v2.y;
        }
        { // tail: Nyquist bin (freq 64)
            float e0 = sC32[tt], e1 = sC32[tt + 11], e2 = sC32[tt + 22];
            float xe0 = Xs[rg * XS_STRIDE + 64];
            float xe1 = Xs[(rg + 23) * XS_STRIDE + 64];
            float xe2 = Xs[(rg + 46) * XS_STRIDE + 64];
            aE00 += e0 * xe0; aE01 += e0 * xe1; aE02 += e0 * xe2;
            aE10 += e1 * xe0; aE11 += e1 * xe1; aE12 += e1 * xe2;
            aE20 += e2 * xe0; aE21 += e2 * xe1; aE22 += e2 * xe2;
        }

        // scatter Y[t] = E+O, Y[64-t] = E-O
        const int t0 = tt, t1 = tt + 11, t2 = tt + 22;
        const int r0 = rg, r1 = rg + 23, r2 = rg + 46;
        Ys[r0*YS_STRIDE + t0]      = aE00 + aO00;
        Ys[r0*YS_STRIDE + 64 - t0] = aE00 - aO00;
        Ys[r1*YS_STRIDE + t0]      = aE01 + aO01;
        Ys[r1*YS_STRIDE + 64 - t0] = aE01 - aO01;
        Ys[r2*YS_STRIDE + t0]      = aE02 + aO02;
        Ys[r2*YS_STRIDE + 64 - t0] = aE02 - aO02;
        Ys[r0*YS_STRIDE + t1]      = aE10 + aO10;
        Ys[r0*YS_STRIDE + 64 - t1] = aE10 - aO10;
        Ys[r1*YS_STRIDE + t1]      = aE11 + aO11;
        Ys[r1*YS_STRIDE + 64 - t1] = aE11 - aO11;
        Ys[r2*YS_STRIDE + t1]      = aE12 + aO12;
        Ys[r2*YS_STRIDE + 64 - t1] = aE12 - aO12;
        Ys[r0*YS_STRIDE + t2]      = aE20 + aO20;
        Ys[r0*YS_STRIDE + 64 - t2] = aE20 - aO20;
        Ys[r1*YS_STRIDE + t2]      = aE21 + aO21;
        Ys[r1*YS_STRIDE + 64 - t2] = aE21 - aO21;
        Ys[r2*YS_STRIDE + t2]      = aE22 + aO22;
        Ys[r2*YS_STRIDE + 64 - t2] = aE22 - aO22;
    }
    __syncthreads();

    // ---- Phase 3: polyphase overlap-add ----
    // out[b,h,j] = (1/512) * sum_k F[64k+j] * Y_{h+5-k}[(64k+j) & 127]
    //   k even -> Y[j], k odd -> Y[64-j] (mirror symmetry)
    const int j  = tid & 63;
    const int hg = tid >> 6;   // 4 h-groups of 16 rows
    const float f0 = sF[j],       f1 = sF[64 + j],  f2 = sF[128 + j];
    const float f3 = sF[192 + j], f4 = sF[256 + j], f5 = sF[320 + j];
    float* outb = out + (size_t)b * ((size_t)TRUE_LEN * 64);

    #pragma unroll 4
    for (int hh = 0; hh < 16; hh++) {
        int hl = hg * 16 + hh;
        int h  = base + hl;
        if (h < TRUE_LEN) {
            float acc = f0 * Ys[(hl + 5) * YS_STRIDE + j]
                      + f1 * Ys[(hl + 4) * YS_STRIDE + 64 - j]
                      + f2 * Ys[(hl + 3) * YS_STRIDE + j]
                      + f3 * Ys[(hl + 2) * YS_STRIDE + 64 - j]
                      + f4 * Ys[(hl + 1) * YS_STRIDE + j]
                      + f5 * Ys[(hl + 0) * YS_STRIDE + 64 - j];
            outb[(size_t)h * 64 + j] = acc * (1.0f / 512.0f);
        }
    }
}

extern "C" void kernel_launch(void* const* d_in, const int* in_sizes, int n_in,
                              void* d_out, int out_size) {
    const float* inp  = (const float*)d_in[0];
    const float* filt = (const float*)d_in[1];
    float* out = (float*)d_out;

    init_tables_kernel<<<9, 256>>>();                   // table entries
    dim3 grid((TRUE_LEN + TILE_H - 1) / TILE_H, B_DIM); // 128 x 16
    subband_kernel<<<grid, 256>>>(inp, filt, out);
}